// round 3
// baseline (speedup 1.0000x reference)
#include <cuda_runtime.h>
#include <math.h>

// ---------------------------------------------------------------------------
// Problem constants
// B=2, C=128, HEADS=8, DH=16
// local grid  S=16,H=32,W=32 -> 16384 tokens/batch, windows 4x8x8=256 of 4x4x4=64
// global grid gS=8,gH=16,gW=16 -> 2048 tokens/batch, windows 256 of 2x2x2=8
// TOPK=4 -> window attention over 64 local + 32 gathered = 96 tokens
// ---------------------------------------------------------------------------

#define SCALE_DIM 0.08838834764831845f   // 128^-0.5
#define SCALE_DH  0.25f                  // 16^-0.5

// -------------------- static scratch (allocation-free) ---------------------
static __device__ float g_xg   [2*2048*128];
static __device__ float g_xl   [2*16384*128];
static __device__ float g_hbuf [2*2048*128];
static __device__ float g_qkvg [2*2048*384];
static __device__ float g_attn [2*2048*128];
static __device__ float g_hid1 [2*2048*512];
static __device__ float g_xg4  [2*2048*128];
static __device__ float g_gwin [2*256*128];
static __device__ float g_qh   [2*256*128];
static __device__ float g_kh   [2*256*128];
static __device__ int   g_tidx [2*256*4];
static __device__ float g_sc   [2*256*96*128];
static __device__ float g_scn  [2*256*96*128];
static __device__ float g_qkvp [2*256*96*384];
static __device__ float g_short[2*256*64*128];
static __device__ float g_awin [2*256*64*128];
static __device__ float g_lwin [2*256*64*128];
static __device__ float g_l    [2*16384*128];
static __device__ float g_lh   [2*16384*128];
static __device__ float g_hid2 [2*16384*512];
static __device__ float g_lfin [2*16384*128];

// -------------------- transpose: per-batch [R,Cc] -> [Cc,R] ----------------
__global__ void transpose2d(const float* __restrict__ in, float* __restrict__ out,
                            int R, int Cc)
{
    __shared__ float tile[32][33];
    size_t boff = (size_t)blockIdx.z * R * Cc;
    int c0 = blockIdx.x * 32, r0 = blockIdx.y * 32;
    int tx = threadIdx.x, ty = threadIdx.y;
    #pragma unroll
    for (int i = 0; i < 32; i += 8)
        tile[ty + i][tx] = in[boff + (size_t)(r0 + ty + i) * Cc + c0 + tx];
    __syncthreads();
    #pragma unroll
    for (int i = 0; i < 32; i += 8)
        out[boff + (size_t)(c0 + ty + i) * R + r0 + tx] = tile[tx][ty + i];
}

// -------------------- LayerNorm over C=128, one warp per token -------------
__global__ void ln_kernel(const float* __restrict__ x, const float* __restrict__ gam,
                          const float* __restrict__ bet, float* __restrict__ y, int ntok)
{
    int warp = (blockIdx.x * blockDim.x + threadIdx.x) >> 5;
    int lane = threadIdx.x & 31;
    if (warp >= ntok) return;
    const float4 xv = *(const float4*)(x + (size_t)warp * 128 + lane * 4);
    float s = xv.x + xv.y + xv.z + xv.w;
    #pragma unroll
    for (int o = 16; o; o >>= 1) s += __shfl_xor_sync(0xffffffffu, s, o);
    float mu = s * (1.f / 128.f);
    float dx = xv.x - mu, dy = xv.y - mu, dz = xv.z - mu, dw = xv.w - mu;
    float v = dx*dx + dy*dy + dz*dz + dw*dw;
    #pragma unroll
    for (int o = 16; o; o >>= 1) v += __shfl_xor_sync(0xffffffffu, v, o);
    float rs = rsqrtf(v * (1.f / 128.f) + 1e-6f);
    float4 gv = *(const float4*)(gam + lane * 4);
    float4 bv = *(const float4*)(bet + lane * 4);
    float4 ov;
    ov.x = dx * rs * gv.x + bv.x;
    ov.y = dy * rs * gv.y + bv.y;
    ov.z = dz * rs * gv.z + bv.z;
    ov.w = dw * rs * gv.w + bv.w;
    *(float4*)(y + (size_t)warp * 128 + lane * 4) = ov;
}

// -------------------- GEMM: C[M,N] = A[M,K] @ W[K,N] + bias (+gelu)(+res) --
// BM=BN=64, BK=16, 256 threads, 4x4 micro-tile. M,N multiples of 64; K of 16.
__global__ void gemm_kernel(const float* __restrict__ A, const float* __restrict__ W,
                            const float* __restrict__ bias, const float* __restrict__ res,
                            float* __restrict__ C, int M, int N, int K, int act)
{
    __shared__ float As[16][65];
    __shared__ float Bs[16][65];
    const int bm = blockIdx.y * 64;
    const int bn = blockIdx.x * 64;
    const int tid = threadIdx.x;
    const int tm = (tid >> 4) * 4;
    const int tn = (tid & 15) * 4;
    const int ar = tid >> 2, ac = (tid & 3) * 4;
    const int wr = tid >> 4, wc = (tid & 15) * 4;
    float acc[4][4] = {};
    for (int k0 = 0; k0 < K; k0 += 16) {
        float4 av = *(const float4*)(A + (size_t)(bm + ar) * K + k0 + ac);
        As[ac + 0][ar] = av.x; As[ac + 1][ar] = av.y;
        As[ac + 2][ar] = av.z; As[ac + 3][ar] = av.w;
        float4 wv = *(const float4*)(W + (size_t)(k0 + wr) * N + bn + wc);
        Bs[wr][wc + 0] = wv.x; Bs[wr][wc + 1] = wv.y;
        Bs[wr][wc + 2] = wv.z; Bs[wr][wc + 3] = wv.w;
        __syncthreads();
        #pragma unroll
        for (int kk = 0; kk < 16; kk++) {
            float a[4], b[4];
            #pragma unroll
            for (int i = 0; i < 4; i++) a[i] = As[kk][tm + i];
            #pragma unroll
            for (int j = 0; j < 4; j++) b[j] = Bs[kk][tn + j];
            #pragma unroll
            for (int i = 0; i < 4; i++)
                #pragma unroll
                for (int j = 0; j < 4; j++)
                    acc[i][j] += a[i] * b[j];
        }
        __syncthreads();
    }
    #pragma unroll
    for (int i = 0; i < 4; i++) {
        #pragma unroll
        for (int j = 0; j < 4; j++) {
            float v = acc[i][j] + bias[bn + tn + j];
            if (act) v = 0.5f * v * (1.f + erff(v * 0.70710678118654752f));
            size_t idx = (size_t)(bm + tm + i) * N + bn + tn + j;
            if (res) v += res[idx];
            C[idx] = v;
        }
    }
}

// -------------------- global flash attention -------------------------------
// qkv: [B,2048,384]  (q @ +h*16, k @ +128+h*16, v @ +256+h*16)
// out: [B,2048,128]  (c = h*16 + d)
// grid (32 qtiles, 8 heads, 2 batch), 512 threads: thread=(q in [0,64), part in [0,8))
__global__ void attn_global(const float* __restrict__ qkv, float* __restrict__ out)
{
    const int b = blockIdx.z, h = blockIdx.y, q0 = blockIdx.x * 64;
    const int tid = threadIdx.x;
    const int q = tid >> 3, part = tid & 7;
    const float* base = qkv + (size_t)b * 2048 * 384;

    float qreg[16];
    {
        const float* qp = base + (size_t)(q0 + q) * 384 + h * 16;
        #pragma unroll
        for (int d = 0; d < 16; d++) qreg[d] = qp[d] * SCALE_DH;
    }
    float m = -1e30f, l = 0.f;
    float o[16];
    #pragma unroll
    for (int d = 0; d < 16; d++) o[d] = 0.f;

    __shared__ float Ks[64][17];
    __shared__ float Vs[64][17];

    for (int c0 = 0; c0 < 2048; c0 += 64) {
        __syncthreads();
        for (int e = tid; e < 1024; e += 512) {
            int r = e >> 4, d = e & 15;
            const float* row = base + (size_t)(c0 + r) * 384 + h * 16;
            Ks[r][d] = row[128 + d];
            Vs[r][d] = row[256 + d];
        }
        __syncthreads();

        float s[8], cmax = -1e30f;
        #pragma unroll
        for (int j = 0; j < 8; j++) {
            int kr = part * 8 + j;
            float a = 0.f;
            #pragma unroll
            for (int d = 0; d < 16; d++) a += qreg[d] * Ks[kr][d];
            s[j] = a;
            cmax = fmaxf(cmax, a);
        }
        #pragma unroll
        for (int off = 4; off; off >>= 1)
            cmax = fmaxf(cmax, __shfl_xor_sync(0xffffffffu, cmax, off));
        float newm = fmaxf(m, cmax);
        float corr = __expf(m - newm);
        float p[8], psum = 0.f;
        #pragma unroll
        for (int j = 0; j < 8; j++) { p[j] = __expf(s[j] - newm); psum += p[j]; }
        #pragma unroll
        for (int off = 4; off; off >>= 1)
            psum += __shfl_xor_sync(0xffffffffu, psum, off);
        l = l * corr + psum;
        #pragma unroll
        for (int d = 0; d < 16; d++) o[d] *= corr;
        #pragma unroll
        for (int j = 0; j < 8; j++) {
            int kr = part * 8 + j;
            #pragma unroll
            for (int d = 0; d < 16; d++) o[d] += p[j] * Vs[kr][d];
        }
        m = newm;
    }
    // combine partial o across the 8 parts (same m,l trajectory on all parts)
    #pragma unroll
    for (int off = 4; off; off >>= 1)
        #pragma unroll
        for (int d = 0; d < 16; d++)
            o[d] += __shfl_xor_sync(0xffffffffu, o[d], off);
    float inv = 1.f / l;
    float* op = out + ((size_t)b * 2048 + q0 + q) * 128 + h * 16;
    op[part * 2 + 0] = o[part * 2 + 0] * inv;
    op[part * 2 + 1] = o[part * 2 + 1] * inv;
}

// -------------------- window mean over global windows ----------------------
__global__ void gwin_kernel()
{
    int w = blockIdx.x, b = blockIdx.y, c = threadIdx.x;
    int i1 = w >> 6, i2 = (w >> 3) & 7, i3 = w & 7;
    float s = 0.f;
    #pragma unroll
    for (int ms = 0; ms < 2; ms++)
        #pragma unroll
        for (int mh = 0; mh < 2; mh++)
            #pragma unroll
            for (int mw = 0; mw < 2; mw++) {
                int n = (i1 * 2 + ms) * 256 + (i2 * 2 + mh) * 16 + (i3 * 2 + mw);
                s += g_xg4[((size_t)b * 2048 + n) * 128 + c];
            }
    g_gwin[((size_t)b * 256 + w) * 128 + c] = s * 0.125f;
}

// -------------------- routing: logits + top-4 indices ----------------------
__global__ void routing_kernel()
{
    int b = blockIdx.y, n = blockIdx.x, mIdx = threadIdx.x;
    __shared__ float lg[256];
    const float* qrow = g_qh + ((size_t)b * 256 + n) * 128;
    const float* krow = g_kh + ((size_t)b * 256 + mIdx) * 128;
    float acc = 0.f;
    #pragma unroll 8
    for (int c = 0; c < 128; c++) acc += qrow[c] * krow[c];
    lg[mIdx] = acc * SCALE_DIM;
    __syncthreads();
    if (mIdx == 0) {
        int* t = g_tidx + (b * 256 + n) * 4;
        for (int kk = 0; kk < 4; kk++) {
            float best = -1e30f; int bi = 0;
            for (int i = 0; i < 256; i++)
                if (lg[i] > best) { best = lg[i]; bi = i; }
            t[kk] = bi;
            lg[bi] = -1e30f;
        }
    }
}

// -------------------- gather: build sc [B,256,96,128] + shortcut -----------
__global__ void gather_kernel()
{
    int t = blockIdx.x, w = blockIdx.y, b = blockIdx.z, c = threadIdx.x;
    float v;
    if (t < 64) {
        int i1 = w >> 6, i2 = (w >> 3) & 7, i3 = w & 7;
        int ms = t >> 4, mh = (t >> 2) & 3, mw = t & 3;
        int n = (i1 * 4 + ms) * 1024 + (i2 * 4 + mh) * 32 + (i3 * 4 + mw);
        v = g_xl[((size_t)b * 16384 + n) * 128 + c];
        g_short[(((size_t)b * 256 + w) * 64 + t) * 128 + c] = v;
    } else {
        int tg = t - 64;
        int kk = tg >> 3, tt = tg & 7;
        int wg = g_tidx[(b * 256 + w) * 4 + kk];
        int j1 = wg >> 6, j2 = (wg >> 3) & 7, j3 = wg & 7;
        int ms = tt >> 2, mh = (tt >> 1) & 1, mw = tt & 1;
        int n = (j1 * 2 + ms) * 256 + (j2 * 2 + mh) * 16 + (j3 * 2 + mw);
        v = g_xg4[((size_t)b * 2048 + n) * 128 + c];
    }
    g_sc[(((size_t)b * 256 + w) * 96 + t) * 128 + c] = v;
}

// -------------------- window attention: 64 queries x 96 keys ---------------
// qkvp [B,256,96,384]; out g_awin [B,256,64,128]
// grid (256 windows, 8 heads, 2 batch), 128 threads: (q in [0,64), part in [0,2))
__global__ void attn_win()
{
    const int w = blockIdx.x, h = blockIdx.y, b = blockIdx.z;
    const int tid = threadIdx.x;
    const float* base = g_qkvp + (size_t)(b * 256 + w) * 96 * 384;

    __shared__ float Ks[96][17];
    __shared__ float Vs[96][17];
    for (int e = tid; e < 1536; e += 128) {
        int r = e >> 4, d = e & 15;
        const float* row = base + (size_t)r * 384 + h * 16;
        Ks[r][d] = row[128 + d];
        Vs[r][d] = row[256 + d];
    }
    __syncthreads();

    const int q = tid >> 1, part = tid & 1;
    float qreg[16];
    {
        const float* qp = base + (size_t)q * 384 + h * 16;
        #pragma unroll
        for (int d = 0; d < 16; d++) qreg[d] = qp[d] * SCALE_DIM;
    }
    // pass 1: max
    float mx = -1e30f;
    for (int kr = part; kr < 96; kr += 2) {
        float a = 0.f;
        #pragma unroll
        for (int d = 0; d < 16; d++) a += qreg[d] * Ks[kr][d];
        mx = fmaxf(mx, a);
    }
    mx = fmaxf(mx, __shfl_xor_sync(0xffffffffu, mx, 1));
    // pass 2: sum + AV
    float sum = 0.f;
    float o[16];
    #pragma unroll
    for (int d = 0; d < 16; d++) o[d] = 0.f;
    for (int kr = part; kr < 96; kr += 2) {
        float a = 0.f;
        #pragma unroll
        for (int d = 0; d < 16; d++) a += qreg[d] * Ks[kr][d];
        float p = __expf(a - mx);
        sum += p;
        #pragma unroll
        for (int d = 0; d < 16; d++) o[d] += p * Vs[kr][d];
    }
    sum += __shfl_xor_sync(0xffffffffu, sum, 1);
    #pragma unroll
    for (int d = 0; d < 16; d++) o[d] += __shfl_xor_sync(0xffffffffu, o[d], 1);
    float inv = 1.f / sum;
    float* op = g_awin + (((size_t)(b * 256 + w)) * 64 + q) * 128 + h * 16;
    #pragma unroll
    for (int d = 0; d < 8; d++) op[part * 8 + d] = o[part * 8 + d] * inv;
}

// -------------------- un-window: g_lwin -> g_l -----------------------------
__global__ void unwindow_kernel()
{
    int t = blockIdx.x, w = blockIdx.y, b = blockIdx.z, c = threadIdx.x;
    int i1 = w >> 6, i2 = (w >> 3) & 7, i3 = w & 7;
    int ms = t >> 4, mh = (t >> 2) & 3, mw = t & 3;
    int n = (i1 * 4 + ms) * 1024 + (i2 * 4 + mh) * 32 + (i3 * 4 + mw);
    g_l[((size_t)b * 16384 + n) * 128 + c] =
        g_lwin[(((size_t)b * 256 + w) * 64 + t) * 128 + c];
}

// ---------------------------------------------------------------------------
extern "C" void kernel_launch(void* const* d_in, const int* in_sizes, int n_in,
                              void* d_out, int out_size)
{
    const float* x_in    = (const float*)d_in[0];
    const float* x_g_in  = (const float*)d_in[1];
    const float* qkv_w   = (const float*)d_in[2];
    const float* qkv_b   = (const float*)d_in[3];
    const float* proj_w  = (const float*)d_in[4];
    const float* proj_b  = (const float*)d_in[5];
    const float* ln_g    = (const float*)d_in[6];
    const float* ln_b    = (const float*)d_in[7];
    const float* mlp_w1  = (const float*)d_in[8];
    const float* mlp_b1  = (const float*)d_in[9];
    const float* mlp_w2  = (const float*)d_in[10];
    const float* mlp_b2  = (const float*)d_in[11];
    const float* rq_w    = (const float*)d_in[12];
    const float* rq_b    = (const float*)d_in[13];
    const float* rk_w    = (const float*)d_in[14];
    const float* rk_b    = (const float*)d_in[15];
    const float* gqkv_w  = (const float*)d_in[16];
    const float* gqkv_b  = (const float*)d_in[17];
    const float* wo_w    = (const float*)d_in[18];
    const float* wo_b    = (const float*)d_in[19];
    const float* mlp2_w1 = (const float*)d_in[20];
    const float* mlp2_b1 = (const float*)d_in[21];
    const float* mlp2_w2 = (const float*)d_in[22];
    const float* mlp2_b2 = (const float*)d_in[23];
    float* out = (float*)d_out;

    float *xg, *xl, *hbuf, *qkvg, *attn, *hid1, *xg4, *gwin, *qh, *kh;
    float *sc, *scn, *qkvp, *shortc, *awin, *lwin, *lbuf, *lh, *hid2, *lfin;
    cudaGetSymbolAddress((void**)&xg,    g_xg);
    cudaGetSymbolAddress((void**)&xl,    g_xl);
    cudaGetSymbolAddress((void**)&hbuf,  g_hbuf);
    cudaGetSymbolAddress((void**)&qkvg,  g_qkvg);
    cudaGetSymbolAddress((void**)&attn,  g_attn);
    cudaGetSymbolAddress((void**)&hid1,  g_hid1);
    cudaGetSymbolAddress((void**)&xg4,   g_xg4);
    cudaGetSymbolAddress((void**)&gwin,  g_gwin);
    cudaGetSymbolAddress((void**)&qh,    g_qh);
    cudaGetSymbolAddress((void**)&kh,    g_kh);
    cudaGetSymbolAddress((void**)&sc,    g_sc);
    cudaGetSymbolAddress((void**)&scn,   g_scn);
    cudaGetSymbolAddress((void**)&qkvp,  g_qkvp);
    cudaGetSymbolAddress((void**)&shortc,g_short);
    cudaGetSymbolAddress((void**)&awin,  g_awin);
    cudaGetSymbolAddress((void**)&lwin,  g_lwin);
    cudaGetSymbolAddress((void**)&lbuf,  g_l);
    cudaGetSymbolAddress((void**)&lh,    g_lh);
    cudaGetSymbolAddress((void**)&hid2,  g_hid2);
    cudaGetSymbolAddress((void**)&lfin,  g_lfin);

    dim3 tb(32, 8);

    // 1) transposes to token-major
    transpose2d<<<dim3(2048 / 32, 128 / 32, 2), tb>>>(x_g_in, xg, 128, 2048);
    transpose2d<<<dim3(16384 / 32, 128 / 32, 2), tb>>>(x_in, xl, 128, 16384);

    // 2) global branch: LN -> qkv -> attention -> proj(+res) -> LN -> MLP(+res)
    ln_kernel<<<4096 / 8, 256>>>(xg, ln_g, ln_b, hbuf, 4096);
    gemm_kernel<<<dim3(384 / 64, 4096 / 64), 256>>>(hbuf, qkv_w, qkv_b, nullptr, qkvg, 4096, 384, 128, 0);
    attn_global<<<dim3(32, 8, 2), 512>>>(qkvg, attn);
    gemm_kernel<<<dim3(128 / 64, 4096 / 64), 256>>>(attn, proj_w, proj_b, xg, xg, 4096, 128, 128, 0);
    ln_kernel<<<4096 / 8, 256>>>(xg, ln_g, ln_b, hbuf, 4096);
    gemm_kernel<<<dim3(512 / 64, 4096 / 64), 256>>>(hbuf, mlp_w1, mlp_b1, nullptr, hid1, 4096, 512, 128, 1);
    gemm_kernel<<<dim3(128 / 64, 4096 / 64), 256>>>(hid1, mlp_w2, mlp_b2, xg, xg4, 4096, 128, 512, 0);

    // 3) routing: window means -> rq/rk -> logits + top-4
    gwin_kernel<<<dim3(256, 2), 128>>>();
    gemm_kernel<<<dim3(128 / 64, 512 / 64), 256>>>(gwin, rq_w, rq_b, nullptr, qh, 512, 128, 128, 0);
    gemm_kernel<<<dim3(128 / 64, 512 / 64), 256>>>(gwin, rk_w, rk_b, nullptr, kh, 512, 128, 128, 0);
    routing_kernel<<<dim3(256, 2), 256>>>();

    // 4) gather concat tokens -> LN -> gqkv -> window attention
    gather_kernel<<<dim3(96, 256, 2), 128>>>();
    ln_kernel<<<49152 / 8, 256>>>(sc, ln_g, ln_b, scn, 49152);
    gemm_kernel<<<dim3(384 / 64, 49152 / 64), 256>>>(scn, gqkv_w, gqkv_b, nullptr, qkvp, 49152, 384, 128, 0);
    attn_win<<<dim3(256, 8, 2), 128>>>();

    // 5) wo(+shortcut) -> un-window -> LN -> MLP2(+res)
    gemm_kernel<<<dim3(128 / 64, 32768 / 64), 256>>>(awin, wo_w, wo_b, shortc, lwin, 32768, 128, 128, 0);
    unwindow_kernel<<<dim3(64, 256, 2), 128>>>();
    ln_kernel<<<32768 / 8, 256>>>(lbuf, ln_g, ln_b, lh, 32768);
    gemm_kernel<<<dim3(512 / 64, 32768 / 64), 256>>>(lh, mlp2_w1, mlp2_b1, nullptr, hid2, 32768, 512, 128, 1);
    gemm_kernel<<<dim3(128 / 64, 32768 / 64), 256>>>(hid2, mlp2_w2, mlp2_b2, lbuf, lfin, 32768, 128, 512, 0);

    // 6) outputs: l_out [2,128,16384] then g_out [2,128,2048]
    transpose2d<<<dim3(128 / 32, 16384 / 32, 2), tb>>>(lfin, out, 16384, 128);
    transpose2d<<<dim3(128 / 32, 2048 / 32, 2), tb>>>(xg4, out + 2 * 128 * 16384 / 1, 2048, 128);
}

// round 4
// speedup vs baseline: 1.5660x; 1.5660x over previous
#include <cuda_runtime.h>
#include <math.h>

// ---------------------------------------------------------------------------
// B=2, C=128, HEADS=8, DH=16
// local 16x32x32 -> 16384 tok/batch, 256 windows of 64; global 8x16x16 -> 2048
// tok/batch, 256 windows of 8. TOPK=4 -> window attn over 64+32=96 tokens.
// ---------------------------------------------------------------------------

#define SCALE_DIM 0.08838834764831845f   // 128^-0.5
#define SCALE_DH  0.25f                  // 16^-0.5

// -------------------- static scratch (allocation-free) ---------------------
static __device__ float g_xg   [2*2048*128];
static __device__ float g_xl   [2*16384*128];
static __device__ float g_hbuf [2*2048*128];
static __device__ float g_qkvg [2*2048*384];
static __device__ float g_attn [2*2048*128];
static __device__ float g_hid1 [2*2048*512];
static __device__ float g_xg4  [2*2048*128];
static __device__ float g_gwin [2*256*128];
static __device__ float g_qh   [2*256*128];
static __device__ float g_kh   [2*256*128];
static __device__ int   g_tidx [2*256*4];
static __device__ float g_sc   [2*256*96*128];
static __device__ float g_scn  [2*256*96*128];
static __device__ float g_qkvp [2*256*96*384];
static __device__ float g_short[2*256*64*128];
static __device__ float g_awin [2*256*64*128];
static __device__ float g_lwin [2*256*64*128];
static __device__ float g_l    [2*16384*128];
static __device__ float g_lh   [2*16384*128];
static __device__ float g_hid2 [2*16384*512];
static __device__ float g_lfin [2*16384*128];

// -------------------- transpose: per-batch [R,Cc] -> [Cc,R] ----------------
__global__ void transpose2d(const float* __restrict__ in, float* __restrict__ out,
                            int R, int Cc)
{
    __shared__ float tile[32][33];
    size_t boff = (size_t)blockIdx.z * R * Cc;
    int c0 = blockIdx.x * 32, r0 = blockIdx.y * 32;
    int tx = threadIdx.x, ty = threadIdx.y;
    #pragma unroll
    for (int i = 0; i < 32; i += 8)
        tile[ty + i][tx] = in[boff + (size_t)(r0 + ty + i) * Cc + c0 + tx];
    __syncthreads();
    #pragma unroll
    for (int i = 0; i < 32; i += 8)
        out[boff + (size_t)(c0 + ty + i) * R + r0 + tx] = tile[tx][ty + i];
}

// -------------------- LayerNorm over C=128, one warp per token -------------
__global__ void ln_kernel(const float* __restrict__ x, const float* __restrict__ gam,
                          const float* __restrict__ bet, float* __restrict__ y, int ntok)
{
    int warp = (blockIdx.x * blockDim.x + threadIdx.x) >> 5;
    int lane = threadIdx.x & 31;
    if (warp >= ntok) return;
    const float4 xv = *(const float4*)(x + (size_t)warp * 128 + lane * 4);
    float s = xv.x + xv.y + xv.z + xv.w;
    #pragma unroll
    for (int o = 16; o; o >>= 1) s += __shfl_xor_sync(0xffffffffu, s, o);
    float mu = s * (1.f / 128.f);
    float dx = xv.x - mu, dy = xv.y - mu, dz = xv.z - mu, dw = xv.w - mu;
    float v = dx*dx + dy*dy + dz*dz + dw*dw;
    #pragma unroll
    for (int o = 16; o; o >>= 1) v += __shfl_xor_sync(0xffffffffu, v, o);
    float rs = rsqrtf(v * (1.f / 128.f) + 1e-6f);
    float4 gv = *(const float4*)(gam + lane * 4);
    float4 bv = *(const float4*)(bet + lane * 4);
    float4 ov;
    ov.x = dx * rs * gv.x + bv.x;
    ov.y = dy * rs * gv.y + bv.y;
    ov.z = dz * rs * gv.z + bv.z;
    ov.w = dw * rs * gv.w + bv.w;
    *(float4*)(y + (size_t)warp * 128 + lane * 4) = ov;
}

// -------------------- GEMM: C[M,N] = A[M,K] @ W[K,N] + bias (+gelu)(+res) --
// BM=BN=128, BK=16, 256 threads, 8x8 micro-tile, float4 smem reads,
// global prefetch. M,N multiples of 128 (N=384 ok: 3 blocks); K multiple of 16.
__global__ __launch_bounds__(256, 2)
void gemm_kernel(const float* __restrict__ A, const float* __restrict__ W,
                 const float* __restrict__ bias, const float* __restrict__ res,
                 float* __restrict__ C, int M, int N, int K, int act)
{
    __shared__ float As[16][132];
    __shared__ float Bs[16][132];
    const int bm = blockIdx.y * 128;
    const int bn = blockIdx.x * 128;
    const int tid = threadIdx.x;
    const int tx = tid & 15, ty = tid >> 4;

    const int arow = tid >> 1, acol = (tid & 1) * 8;
    const int brow = tid >> 4, bcol = (tid & 15) * 8;

    const float* Aptr = A + (size_t)(bm + arow) * K + acol;
    const float* Wptr = W + (size_t)brow * N + bn + bcol;

    float acc[8][8] = {};

    float4 a0 = *(const float4*)(Aptr);
    float4 a1 = *(const float4*)(Aptr + 4);
    float4 b0 = *(const float4*)(Wptr);
    float4 b1 = *(const float4*)(Wptr + 4);

    for (int k0 = 0; k0 < K; k0 += 16) {
        As[acol + 0][arow] = a0.x; As[acol + 1][arow] = a0.y;
        As[acol + 2][arow] = a0.z; As[acol + 3][arow] = a0.w;
        As[acol + 4][arow] = a1.x; As[acol + 5][arow] = a1.y;
        As[acol + 6][arow] = a1.z; As[acol + 7][arow] = a1.w;
        *(float4*)&Bs[brow][bcol] = b0;
        *(float4*)&Bs[brow][bcol + 4] = b1;
        __syncthreads();
        if (k0 + 16 < K) {
            a0 = *(const float4*)(Aptr + k0 + 16);
            a1 = *(const float4*)(Aptr + k0 + 20);
            b0 = *(const float4*)(Wptr + (size_t)(k0 + 16) * N);
            b1 = *(const float4*)(Wptr + (size_t)(k0 + 16) * N + 4);
        }
        #pragma unroll
        for (int kk = 0; kk < 16; kk++) {
            float a[8], b[8];
            *(float4*)(a)     = *(const float4*)&As[kk][ty * 4];
            *(float4*)(a + 4) = *(const float4*)&As[kk][64 + ty * 4];
            *(float4*)(b)     = *(const float4*)&Bs[kk][tx * 4];
            *(float4*)(b + 4) = *(const float4*)&Bs[kk][64 + tx * 4];
            #pragma unroll
            for (int i = 0; i < 8; i++)
                #pragma unroll
                for (int j = 0; j < 8; j++)
                    acc[i][j] += a[i] * b[j];
        }
        __syncthreads();
    }

    float4 bs0 = *(const float4*)(bias + bn + tx * 4);
    float4 bs1 = *(const float4*)(bias + bn + 64 + tx * 4);
    #pragma unroll
    for (int ih = 0; ih < 2; ih++) {
        #pragma unroll
        for (int ii = 0; ii < 4; ii++) {
            int i = ih * 4 + ii;
            int row = bm + ih * 64 + ty * 4 + ii;
            #pragma unroll
            for (int jh = 0; jh < 2; jh++) {
                int col = bn + jh * 64 + tx * 4;
                float4 bb = jh ? bs1 : bs0;
                float4 v;
                v.x = acc[i][jh * 4 + 0] + bb.x;
                v.y = acc[i][jh * 4 + 1] + bb.y;
                v.z = acc[i][jh * 4 + 2] + bb.z;
                v.w = acc[i][jh * 4 + 3] + bb.w;
                if (act) {
                    v.x = 0.5f * v.x * (1.f + erff(v.x * 0.70710678118654752f));
                    v.y = 0.5f * v.y * (1.f + erff(v.y * 0.70710678118654752f));
                    v.z = 0.5f * v.z * (1.f + erff(v.z * 0.70710678118654752f));
                    v.w = 0.5f * v.w * (1.f + erff(v.w * 0.70710678118654752f));
                }
                size_t idx = (size_t)row * N + col;
                if (res) {
                    float4 r4 = *(const float4*)(res + idx);
                    v.x += r4.x; v.y += r4.y; v.z += r4.z; v.w += r4.w;
                }
                *(float4*)(C + idx) = v;
            }
        }
    }
}

// -------------------- global flash attention -------------------------------
// qkv: [B,2048,384]; out: [B,2048,128]
// grid (32 qtiles, 8 heads, 2 batch), 512 threads: thread=(q in [0,64), part in [0,8))
// part handles rows {part, part+8, ..., part+56} of each 64-row K tile
// (strided so the 8 parts' float4 LDS hit distinct bank phases).
__global__ void attn_global(const float* __restrict__ qkv, float* __restrict__ out)
{
    const int b = blockIdx.z, h = blockIdx.y, q0 = blockIdx.x * 64;
    const int tid = threadIdx.x;
    const int q = tid >> 3, part = tid & 7;
    const float* base = qkv + (size_t)b * 2048 * 384;

    float4 qv[4];
    {
        const float4* qp = (const float4*)(base + (size_t)(q0 + q) * 384 + h * 16);
        #pragma unroll
        for (int i = 0; i < 4; i++) {
            qv[i] = qp[i];
            qv[i].x *= SCALE_DH; qv[i].y *= SCALE_DH;
            qv[i].z *= SCALE_DH; qv[i].w *= SCALE_DH;
        }
    }
    float m = -1e30f, l = 0.f;
    float o[16];
    #pragma unroll
    for (int d = 0; d < 16; d++) o[d] = 0.f;

    __shared__ float Ks[64][20];   // 80B rows, 16B aligned
    __shared__ float Vs[64][20];

    for (int c0 = 0; c0 < 2048; c0 += 64) {
        __syncthreads();
        {
            int mat = tid >> 8, idx = tid & 255;
            int r = idx >> 2, i = idx & 3;
            const float* row = base + (size_t)(c0 + r) * 384 + h * 16 + (mat ? 256 : 128);
            float* dst = mat ? Vs[r] : Ks[r];
            ((float4*)dst)[i] = *(const float4*)(row + i * 4);
        }
        __syncthreads();

        float s[8], cmax = -1e30f;
        #pragma unroll
        for (int j = 0; j < 8; j++) {
            int kr = part + j * 8;
            const float4* Kr = (const float4*)Ks[kr];
            float4 k0v = Kr[0], k1v = Kr[1], k2v = Kr[2], k3v = Kr[3];
            float a = qv[0].x*k0v.x + qv[0].y*k0v.y + qv[0].z*k0v.z + qv[0].w*k0v.w
                    + qv[1].x*k1v.x + qv[1].y*k1v.y + qv[1].z*k1v.z + qv[1].w*k1v.w
                    + qv[2].x*k2v.x + qv[2].y*k2v.y + qv[2].z*k2v.z + qv[2].w*k2v.w
                    + qv[3].x*k3v.x + qv[3].y*k3v.y + qv[3].z*k3v.z + qv[3].w*k3v.w;
            s[j] = a;
            cmax = fmaxf(cmax, a);
        }
        #pragma unroll
        for (int off = 4; off; off >>= 1)
            cmax = fmaxf(cmax, __shfl_xor_sync(0xffffffffu, cmax, off));
        float newm = fmaxf(m, cmax);
        float corr = __expf(m - newm);
        float p[8], psum = 0.f;
        #pragma unroll
        for (int j = 0; j < 8; j++) { p[j] = __expf(s[j] - newm); psum += p[j]; }
        #pragma unroll
        for (int off = 4; off; off >>= 1)
            psum += __shfl_xor_sync(0xffffffffu, psum, off);
        l = l * corr + psum;
        #pragma unroll
        for (int d = 0; d < 16; d++) o[d] *= corr;
        #pragma unroll
        for (int j = 0; j < 8; j++) {
            int kr = part + j * 8;
            const float4* Vr = (const float4*)Vs[kr];
            float4 v0 = Vr[0], v1 = Vr[1], v2 = Vr[2], v3 = Vr[3];
            float pj = p[j];
            o[0]  += pj * v0.x; o[1]  += pj * v0.y; o[2]  += pj * v0.z; o[3]  += pj * v0.w;
            o[4]  += pj * v1.x; o[5]  += pj * v1.y; o[6]  += pj * v1.z; o[7]  += pj * v1.w;
            o[8]  += pj * v2.x; o[9]  += pj * v2.y; o[10] += pj * v2.z; o[11] += pj * v2.w;
            o[12] += pj * v3.x; o[13] += pj * v3.y; o[14] += pj * v3.z; o[15] += pj * v3.w;
        }
        m = newm;
    }
    #pragma unroll
    for (int off = 4; off; off >>= 1)
        #pragma unroll
        for (int d = 0; d < 16; d++)
            o[d] += __shfl_xor_sync(0xffffffffu, o[d], off);
    float inv = 1.f / l;
    float* op = out + ((size_t)b * 2048 + q0 + q) * 128 + h * 16;
    op[part * 2 + 0] = o[part * 2 + 0] * inv;
    op[part * 2 + 1] = o[part * 2 + 1] * inv;
}

// -------------------- window mean over global windows ----------------------
__global__ void gwin_kernel()
{
    int w = blockIdx.x, b = blockIdx.y, c = threadIdx.x;
    int i1 = w >> 6, i2 = (w >> 3) & 7, i3 = w & 7;
    float s = 0.f;
    #pragma unroll
    for (int ms = 0; ms < 2; ms++)
        #pragma unroll
        for (int mh = 0; mh < 2; mh++)
            #pragma unroll
            for (int mw = 0; mw < 2; mw++) {
                int n = (i1 * 2 + ms) * 256 + (i2 * 2 + mh) * 16 + (i3 * 2 + mw);
                s += g_xg4[((size_t)b * 2048 + n) * 128 + c];
            }
    g_gwin[((size_t)b * 256 + w) * 128 + c] = s * 0.125f;
}

// -------------------- routing: logits + top-4 indices ----------------------
__global__ void routing_kernel()
{
    int b = blockIdx.y, n = blockIdx.x, mIdx = threadIdx.x;
    __shared__ float lg[256];
    const float* qrow = g_qh + ((size_t)b * 256 + n) * 128;
    const float* krow = g_kh + ((size_t)b * 256 + mIdx) * 128;
    float acc = 0.f;
    #pragma unroll 8
    for (int c = 0; c < 128; c++) acc += qrow[c] * krow[c];
    lg[mIdx] = acc * SCALE_DIM;
    __syncthreads();
    if (mIdx == 0) {
        int* t = g_tidx + (b * 256 + n) * 4;
        for (int kk = 0; kk < 4; kk++) {
            float best = -1e30f; int bi = 0;
            for (int i = 0; i < 256; i++)
                if (lg[i] > best) { best = lg[i]; bi = i; }
            t[kk] = bi;
            lg[bi] = -1e30f;
        }
    }
}

// -------------------- gather: build sc [B,256,96,128] + shortcut -----------
__global__ void gather_kernel()
{
    int t = blockIdx.x, w = blockIdx.y, b = blockIdx.z, c = threadIdx.x;
    float v;
    if (t < 64) {
        int i1 = w >> 6, i2 = (w >> 3) & 7, i3 = w & 7;
        int ms = t >> 4, mh = (t >> 2) & 3, mw = t & 3;
        int n = (i1 * 4 + ms) * 1024 + (i2 * 4 + mh) * 32 + (i3 * 4 + mw);
        v = g_xl[((size_t)b * 16384 + n) * 128 + c];
        g_short[(((size_t)b * 256 + w) * 64 + t) * 128 + c] = v;
    } else {
        int tg = t - 64;
        int kk = tg >> 3, tt = tg & 7;
        int wg = g_tidx[(b * 256 + w) * 4 + kk];
        int j1 = wg >> 6, j2 = (wg >> 3) & 7, j3 = wg & 7;
        int ms = tt >> 2, mh = (tt >> 1) & 1, mw = tt & 1;
        int n = (j1 * 2 + ms) * 256 + (j2 * 2 + mh) * 16 + (j3 * 2 + mw);
        v = g_xg4[((size_t)b * 2048 + n) * 128 + c];
    }
    g_sc[(((size_t)b * 256 + w) * 96 + t) * 128 + c] = v;
}

// -------------------- window attention: 64 queries x 96 keys ---------------
// grid (256 windows, 8 heads, 2 batch), 128 threads: (q in [0,64), part in [0,2))
__global__ void attn_win()
{
    const int w = blockIdx.x, h = blockIdx.y, b = blockIdx.z;
    const int tid = threadIdx.x;
    const float* base = g_qkvp + (size_t)(b * 256 + w) * 96 * 384;

    __shared__ float Ks[96][20];
    __shared__ float Vs[96][20];
    for (int e = tid; e < 384; e += 128) {
        int r = e >> 2, i = e & 3;
        const float* row = base + (size_t)r * 384 + h * 16;
        ((float4*)Ks[r])[i] = *(const float4*)(row + 128 + i * 4);
        ((float4*)Vs[r])[i] = *(const float4*)(row + 256 + i * 4);
    }
    __syncthreads();

    const int q = tid >> 1, part = tid & 1;
    float4 qv[4];
    {
        const float4* qp = (const float4*)(base + (size_t)q * 384 + h * 16);
        #pragma unroll
        for (int i = 0; i < 4; i++) {
            qv[i] = qp[i];
            qv[i].x *= SCALE_DIM; qv[i].y *= SCALE_DIM;
            qv[i].z *= SCALE_DIM; qv[i].w *= SCALE_DIM;
        }
    }
    // pass 1: max
    float mx = -1e30f;
    for (int kr = part; kr < 96; kr += 2) {
        const float4* Kr = (const float4*)Ks[kr];
        float4 k0v = Kr[0], k1v = Kr[1], k2v = Kr[2], k3v = Kr[3];
        float a = qv[0].x*k0v.x + qv[0].y*k0v.y + qv[0].z*k0v.z + qv[0].w*k0v.w
                + qv[1].x*k1v.x + qv[1].y*k1v.y + qv[1].z*k1v.z + qv[1].w*k1v.w
                + qv[2].x*k2v.x + qv[2].y*k2v.y + qv[2].z*k2v.z + qv[2].w*k2v.w
                + qv[3].x*k3v.x + qv[3].y*k3v.y + qv[3].z*k3v.z + qv[3].w*k3v.w;
        mx = fmaxf(mx, a);
    }
    mx = fmaxf(mx, __shfl_xor_sync(0xffffffffu, mx, 1));
    // pass 2: sum + AV
    float sum = 0.f;
    float o[16];
    #pragma unroll
    for (int d = 0; d < 16; d++) o[d] = 0.f;
    for (int kr = part; kr < 96; kr += 2) {
        const float4* Kr = (const float4*)Ks[kr];
        float4 k0v = Kr[0], k1v = Kr[1], k2v = Kr[2], k3v = Kr[3];
        float a = qv[0].x*k0v.x + qv[0].y*k0v.y + qv[0].z*k0v.z + qv[0].w*k0v.w
                + qv[1].x*k1v.x + qv[1].y*k1v.y + qv[1].z*k1v.z + qv[1].w*k1v.w
                + qv[2].x*k2v.x + qv[2].y*k2v.y + qv[2].z*k2v.z + qv[2].w*k2v.w
                + qv[3].x*k3v.x + qv[3].y*k3v.y + qv[3].z*k3v.z + qv[3].w*k3v.w;
        float p = __expf(a - mx);
        sum += p;
        const float4* Vr = (const float4*)Vs[kr];
        float4 v0 = Vr[0], v1 = Vr[1], v2 = Vr[2], v3 = Vr[3];
        o[0]  += p * v0.x; o[1]  += p * v0.y; o[2]  += p * v0.z; o[3]  += p * v0.w;
        o[4]  += p * v1.x; o[5]  += p * v1.y; o[6]  += p * v1.z; o[7]  += p * v1.w;
        o[8]  += p * v2.x; o[9]  += p * v2.y; o[10] += p * v2.z; o[11] += p * v2.w;
        o[12] += p * v3.x; o[13] += p * v3.y; o[14] += p * v3.z; o[15] += p * v3.w;
    }
    sum += __shfl_xor_sync(0xffffffffu, sum, 1);
    #pragma unroll
    for (int d = 0; d < 16; d++) o[d] += __shfl_xor_sync(0xffffffffu, o[d], 1);
    float inv = 1.f / sum;
    float* op = g_awin + (((size_t)(b * 256 + w)) * 64 + q) * 128 + h * 16;
    #pragma unroll
    for (int d = 0; d < 8; d++) op[part * 8 + d] = o[part * 8 + d] * inv;
}

// -------------------- un-window: g_lwin -> g_l -----------------------------
__global__ void unwindow_kernel()
{
    int t = blockIdx.x, w = blockIdx.y, b = blockIdx.z, c = threadIdx.x;
    int i1 = w >> 6, i2 = (w >> 3) & 7, i3 = w & 7;
    int ms = t >> 4, mh = (t >> 2) & 3, mw = t & 3;
    int n = (i1 * 4 + ms) * 1024 + (i2 * 4 + mh) * 32 + (i3 * 4 + mw);
    g_l[((size_t)b * 16384 + n) * 128 + c] =
        g_lwin[(((size_t)b * 256 + w) * 64 + t) * 128 + c];
}

// ---------------------------------------------------------------------------
extern "C" void kernel_launch(void* const* d_in, const int* in_sizes, int n_in,
                              void* d_out, int out_size)
{
    const float* x_in    = (const float*)d_in[0];
    const float* x_g_in  = (const float*)d_in[1];
    const float* qkv_w   = (const float*)d_in[2];
    const float* qkv_b   = (const float*)d_in[3];
    const float* proj_w  = (const float*)d_in[4];
    const float* proj_b  = (const float*)d_in[5];
    const float* ln_g    = (const float*)d_in[6];
    const float* ln_b    = (const float*)d_in[7];
    const float* mlp_w1  = (const float*)d_in[8];
    const float* mlp_b1  = (const float*)d_in[9];
    const float* mlp_w2  = (const float*)d_in[10];
    const float* mlp_b2  = (const float*)d_in[11];
    const float* rq_w    = (const float*)d_in[12];
    const float* rq_b    = (const float*)d_in[13];
    const float* rk_w    = (const float*)d_in[14];
    const float* rk_b    = (const float*)d_in[15];
    const float* gqkv_w  = (const float*)d_in[16];
    const float* gqkv_b  = (const float*)d_in[17];
    const float* wo_w    = (const float*)d_in[18];
    const float* wo_b    = (const float*)d_in[19];
    const float* mlp2_w1 = (const float*)d_in[20];
    const float* mlp2_b1 = (const float*)d_in[21];
    const float* mlp2_w2 = (const float*)d_in[22];
    const float* mlp2_b2 = (const float*)d_in[23];
    float* out = (float*)d_out;

    float *xg, *xl, *hbuf, *qkvg, *attn, *hid1, *xg4, *gwin, *qh, *kh;
    float *sc, *scn, *qkvp, *shortc, *awin, *lwin, *lbuf, *lh, *hid2, *lfin;
    cudaGetSymbolAddress((void**)&xg,    g_xg);
    cudaGetSymbolAddress((void**)&xl,    g_xl);
    cudaGetSymbolAddress((void**)&hbuf,  g_hbuf);
    cudaGetSymbolAddress((void**)&qkvg,  g_qkvg);
    cudaGetSymbolAddress((void**)&attn,  g_attn);
    cudaGetSymbolAddress((void**)&hid1,  g_hid1);
    cudaGetSymbolAddress((void**)&xg4,   g_xg4);
    cudaGetSymbolAddress((void**)&gwin,  g_gwin);
    cudaGetSymbolAddress((void**)&qh,    g_qh);
    cudaGetSymbolAddress((void**)&kh,    g_kh);
    cudaGetSymbolAddress((void**)&sc,    g_sc);
    cudaGetSymbolAddress((void**)&scn,   g_scn);
    cudaGetSymbolAddress((void**)&qkvp,  g_qkvp);
    cudaGetSymbolAddress((void**)&shortc,g_short);
    cudaGetSymbolAddress((void**)&awin,  g_awin);
    cudaGetSymbolAddress((void**)&lwin,  g_lwin);
    cudaGetSymbolAddress((void**)&lbuf,  g_l);
    cudaGetSymbolAddress((void**)&lh,    g_lh);
    cudaGetSymbolAddress((void**)&hid2,  g_hid2);
    cudaGetSymbolAddress((void**)&lfin,  g_lfin);

    dim3 tb(32, 8);

    // 1) transposes to token-major
    transpose2d<<<dim3(2048 / 32, 128 / 32, 2), tb>>>(x_g_in, xg, 128, 2048);
    transpose2d<<<dim3(16384 / 32, 128 / 32, 2), tb>>>(x_in, xl, 128, 16384);

    // 2) global branch: LN -> qkv -> attention -> proj(+res) -> LN -> MLP(+res)
    ln_kernel<<<4096 / 8, 256>>>(xg, ln_g, ln_b, hbuf, 4096);
    gemm_kernel<<<dim3(3, 32), 256>>>(hbuf, qkv_w, qkv_b, nullptr, qkvg, 4096, 384, 128, 0);
    attn_global<<<dim3(32, 8, 2), 512>>>(qkvg, attn);
    gemm_kernel<<<dim3(1, 32), 256>>>(attn, proj_w, proj_b, xg, xg, 4096, 128, 128, 0);
    ln_kernel<<<4096 / 8, 256>>>(xg, ln_g, ln_b, hbuf, 4096);
    gemm_kernel<<<dim3(4, 32), 256>>>(hbuf, mlp_w1, mlp_b1, nullptr, hid1, 4096, 512, 128, 1);
    gemm_kernel<<<dim3(1, 32), 256>>>(hid1, mlp_w2, mlp_b2, xg, xg4, 4096, 128, 512, 0);

    // 3) routing: window means -> rq/rk -> logits + top-4
    gwin_kernel<<<dim3(256, 2), 128>>>();
    gemm_kernel<<<dim3(1, 4), 256>>>(gwin, rq_w, rq_b, nullptr, qh, 512, 128, 128, 0);
    gemm_kernel<<<dim3(1, 4), 256>>>(gwin, rk_w, rk_b, nullptr, kh, 512, 128, 128, 0);
    routing_kernel<<<dim3(256, 2), 256>>>();

    // 4) gather concat tokens -> LN -> gqkv -> window attention
    gather_kernel<<<dim3(96, 256, 2), 128>>>();
    ln_kernel<<<49152 / 8, 256>>>(sc, ln_g, ln_b, scn, 49152);
    gemm_kernel<<<dim3(3, 384), 256>>>(scn, gqkv_w, gqkv_b, nullptr, qkvp, 49152, 384, 128, 0);
    attn_win<<<dim3(256, 8, 2), 128>>>();

    // 5) wo(+shortcut) -> un-window -> LN -> MLP2(+res)
    gemm_kernel<<<dim3(1, 256), 256>>>(awin, wo_w, wo_b, shortc, lwin, 32768, 128, 128, 0);
    unwindow_kernel<<<dim3(64, 256, 2), 128>>>();
    ln_kernel<<<32768 / 8, 256>>>(lbuf, ln_g, ln_b, lh, 32768);
    gemm_kernel<<<dim3(4, 256), 256>>>(lh, mlp2_w1, mlp2_b1, nullptr, hid2, 32768, 512, 128, 1);
    gemm_kernel<<<dim3(1, 256), 256>>>(hid2, mlp2_w2, mlp2_b2, lbuf, lfin, 32768, 128, 512, 0);

    // 6) outputs: l_out [2,128,16384] then g_out [2,128,2048]
    transpose2d<<<dim3(128 / 32, 16384 / 32, 2), tb>>>(lfin, out, 16384, 128);
    transpose2d<<<dim3(128 / 32, 2048 / 32, 2), tb>>>(xg4, out + 2 * 128 * 16384, 2048, 128);
}